// round 14
// baseline (speedup 1.0000x reference)
#include <cuda_runtime.h>
#include <cuda_fp16.h>
#include <cstdint>

#define KD 4096   // input features
#define ND 4096   // output features
#define MD 8192   // rows of x

// Static device scratch.
static __device__ __half g_W[(size_t)ND * KD];  // dequantized Wt[n][k], 32MB
static __device__ __half g_X[(size_t)MD * KD];  // x fp16, 64MB

// ---------------------------------------------------------------------------
// Merged prologue: blocks [0, 16384) convert x fp32->fp16 (8 elems/thread),
// blocks [16384, 17408) dequant int4 -> fp16 Wt via smem transpose.
// Both are DRAM-bound; merging overlaps them and drops one launch boundary.
// ---------------------------------------------------------------------------
constexpr int CONV_BLOCKS = (int)((size_t)MD * KD / (8 * 256));   // 16384
constexpr int DQ_PADK = 136;   // 128 k halfs + 8 pad -> 272B rows

__global__ void __launch_bounds__(256)
prologue_kernel(const float* __restrict__ x,
                const int* __restrict__ qw,
                const float* __restrict__ scales,
                const float* __restrict__ qzeros) {
    __shared__ __half tile[128 * DQ_PADK];   // 34KB (unused by convert blocks)

    if (blockIdx.x < CONV_BLOCKS) {
        // ---- convert x ----
        size_t i = ((size_t)blockIdx.x * blockDim.x + threadIdx.x) * 8;
        float4 a = *reinterpret_cast<const float4*>(x + i);
        float4 b = *reinterpret_cast<const float4*>(x + i + 4);
        __half h[8];
        h[0] = __float2half_rn(a.x); h[1] = __float2half_rn(a.y);
        h[2] = __float2half_rn(a.z); h[3] = __float2half_rn(a.w);
        h[4] = __float2half_rn(b.x); h[5] = __float2half_rn(b.y);
        h[6] = __float2half_rn(b.z); h[7] = __float2half_rn(b.w);
        *reinterpret_cast<uint4*>(&g_X[i]) = *reinterpret_cast<const uint4*>(h);
        return;
    }

    // ---- dequant (R10 proven layout) ----
    const int blk = blockIdx.x - CONV_BLOCKS;     // 0..1023
    const int tid = threadIdx.x;
    const int n0 = (blk & 31) * 128;
    const int r0 = (blk >> 5) * 16;

    const int n_loc = tid & 127;
    const int r_hi  = tid >> 7;
    const int n = n0 + n_loc;

#pragma unroll
    for (int p = 0; p < 8; p++) {
        int r = r0 + r_hi * 8 + p;
        int g = r >> 3;
        uint32_t q = (uint32_t)qw[r * ND + n];
        __half hs = __float2half_rn(scales[g * ND + n]);
        __half hz = __float2half_rn(qzeros[g * ND + n]);
        __half hzs = __hmul(hz, hs);
        __half h[8];
#pragma unroll
        for (int i = 0; i < 8; i++) {
            __half hw = __float2half_rn((float)((q >> (4 * i)) & 15u));
            h[i] = __hsub(__hmul(hs, hw), hzs);
        }
        *reinterpret_cast<uint4*>(&tile[n_loc * DQ_PADK + (r_hi * 8 + p) * 8]) =
            *reinterpret_cast<const uint4*>(h);
    }
    __syncthreads();

    const int wn = tid >> 1;
    const int k0 = r0 * 8;
#pragma unroll
    for (int pass = 0; pass < 8; pass++) {
        int c = (tid & 1) + pass * 2;
        uint4 v = *reinterpret_cast<const uint4*>(&tile[wn * DQ_PADK + c * 8]);
        *reinterpret_cast<uint4*>(&g_W[(size_t)(n0 + wn) * KD + k0 + c * 8]) = v;
    }
}

// ---------------------------------------------------------------------------
// GEMM: C = X * Wt^T + bias. BM=BN=128, BK=32, 128 threads = 4 warps (2x2),
// warp tile 64x64. 5-stage cp.async pipeline (4 chunks of lookahead).
// Single fragment buffer. 2 CTAs/SM. (R10 champion, unchanged.)
// ---------------------------------------------------------------------------
constexpr int BM = 128, BN = 128, BK = 32, STAGES = 5;
constexpr int LDS_ = BK + 8;                            // 40 halfs per row
constexpr int SMEM_HALFS = STAGES * (BM + BN) * LDS_;   // 51200 halfs = 100KB

__device__ __forceinline__ void cp16(uint32_t sdst, const void* g) {
    asm volatile("cp.async.cg.shared.global [%0], [%1], 16;\n" :: "r"(sdst), "l"(g));
}

__global__ void __launch_bounds__(128, 2)
gemm_kernel(const float* __restrict__ bias,
            float* __restrict__ C) {
    extern __shared__ __half sm[];
    __half* As = sm;
    __half* Bs = sm + STAGES * BM * LDS_;

    const int tid  = threadIdx.x;
    const int lane = tid & 31;
    const int warp = tid >> 5;
    const int wm = warp & 1;
    const int wn = warp >> 1;
    const int bm = blockIdx.y * BM;
    const int bn = blockIdx.x * BN;

    const uint32_t as_base = (uint32_t)__cvta_generic_to_shared(As);
    const uint32_t bs_base = (uint32_t)__cvta_generic_to_shared(Bs);

    float acc[4][8][4];
#pragma unroll
    for (int i = 0; i < 4; i++)
#pragma unroll
        for (int j = 0; j < 8; j++)
#pragma unroll
            for (int t = 0; t < 4; t++) acc[i][j][t] = 0.f;

    auto load_stage = [&](int kt, int s) {
        int k0 = kt * BK;
#pragma unroll
        for (int i = 0; i < 4; i++) {
            int cid = i * 128 + tid;
            int row = cid >> 2;
            int ch  = cid & 3;
            cp16(as_base + (uint32_t)((s * BM + row) * LDS_ + ch * 8) * 2,
                 g_X + (size_t)(bm + row) * KD + k0 + ch * 8);
        }
#pragma unroll
        for (int i = 0; i < 4; i++) {
            int cid = i * 128 + tid;
            int row = cid >> 2;
            int ch  = cid & 3;
            cp16(bs_base + (uint32_t)((s * BN + row) * LDS_ + ch * 8) * 2,
                 g_W + (size_t)(bn + row) * KD + k0 + ch * 8);
        }
        asm volatile("cp.async.commit_group;\n");
    };

    auto compute_stage = [&](int s) {
#pragma unroll
        for (int ks = 0; ks < 2; ks++) {
            uint32_t a[4][4];
            uint32_t b[8][2];
            int ar = wm * 64 + (lane & 15);
            int ac = ks * 16 + ((lane >> 4) << 3);
#pragma unroll
            for (int mi = 0; mi < 4; mi++) {
                uint32_t addr = as_base +
                    (uint32_t)((s * BM + ar + mi * 16) * LDS_ + ac) * 2;
                asm volatile(
                    "ldmatrix.sync.aligned.m8n8.x4.shared.b16 {%0,%1,%2,%3}, [%4];\n"
                    : "=r"(a[mi][0]), "=r"(a[mi][1]), "=r"(a[mi][2]), "=r"(a[mi][3])
                    : "r"(addr));
            }
            int br = wn * 64 + ((lane >> 4) << 3) + (lane & 7);
            int bc = ks * 16 + (((lane >> 3) & 1) << 3);
#pragma unroll
            for (int nh = 0; nh < 4; nh++) {
                uint32_t addr = bs_base +
                    (uint32_t)((s * BN + br + nh * 16) * LDS_ + bc) * 2;
                asm volatile(
                    "ldmatrix.sync.aligned.m8n8.x4.shared.b16 {%0,%1,%2,%3}, [%4];\n"
                    : "=r"(b[nh * 2][0]), "=r"(b[nh * 2][1]),
                      "=r"(b[nh * 2 + 1][0]), "=r"(b[nh * 2 + 1][1])
                    : "r"(addr));
            }
#pragma unroll
            for (int mi = 0; mi < 4; mi++)
#pragma unroll
                for (int ni = 0; ni < 8; ni++) {
                    asm volatile(
                        "mma.sync.aligned.m16n8k16.row.col.f32.f16.f16.f32 "
                        "{%0,%1,%2,%3}, {%4,%5,%6,%7}, {%8,%9}, {%0,%1,%2,%3};\n"
                        : "+f"(acc[mi][ni][0]), "+f"(acc[mi][ni][1]),
                          "+f"(acc[mi][ni][2]), "+f"(acc[mi][ni][3])
                        : "r"(a[mi][0]), "r"(a[mi][1]), "r"(a[mi][2]), "r"(a[mi][3]),
                          "r"(b[ni][0]), "r"(b[ni][1]));
                }
        }
    };

    const int KT = KD / BK;   // 128
#pragma unroll
    for (int s = 0; s < STAGES - 1; s++) load_stage(s, s);

    int cs = 0;
    int ls = STAGES - 1;
    for (int kt = 0; kt < KT; kt++) {
        asm volatile("cp.async.wait_group %0;\n" :: "n"(STAGES - 2));
        __syncthreads();
        int nk = kt + STAGES - 1;
        if (nk < KT) load_stage(nk, ls);
        else         asm volatile("cp.async.commit_group;\n");
        compute_stage(cs);
        if (++cs == STAGES) cs = 0;
        if (++ls == STAGES) ls = 0;
    }

    // Epilogue: fp16(acc) + fp16(bias), store fp32 (mirrors reference rounding).
    const int group = lane >> 2, tig = lane & 3;
#pragma unroll
    for (int mi = 0; mi < 4; mi++) {
        int row = bm + wm * 64 + mi * 16 + group;
#pragma unroll
        for (int ni = 0; ni < 8; ni++) {
            int col = bn + wn * 64 + ni * 8 + tig * 2;
            float2 bb = *reinterpret_cast<const float2*>(&bias[col]);
            __half hb0 = __float2half_rn(bb.x);
            __half hb1 = __float2half_rn(bb.y);
            float2 r0, r1;
            r0.x = __half2float(__hadd(__float2half_rn(acc[mi][ni][0]), hb0));
            r0.y = __half2float(__hadd(__float2half_rn(acc[mi][ni][1]), hb1));
            r1.x = __half2float(__hadd(__float2half_rn(acc[mi][ni][2]), hb0));
            r1.y = __half2float(__hadd(__float2half_rn(acc[mi][ni][3]), hb1));
            *reinterpret_cast<float2*>(&C[(size_t)row * ND + col]) = r0;
            *reinterpret_cast<float2*>(&C[(size_t)(row + 8) * ND + col]) = r1;
        }
    }
}

// ---------------------------------------------------------------------------
extern "C" void kernel_launch(void* const* d_in, const int* in_sizes, int n_in,
                              void* d_out, int out_size) {
    const float* x      = (const float*)d_in[0];
    const int*   qw     = (const int*)d_in[1];
    const float* scales = (const float*)d_in[2];
    const float* qzeros = (const float*)d_in[3];
    const float* bias   = (const float*)d_in[4];

    // Merged prologue: 16384 convert blocks + 1024 dequant blocks.
    prologue_kernel<<<CONV_BLOCKS + 1024, 256>>>(x, qw, scales, qzeros);

    size_t smem = (size_t)SMEM_HALFS * sizeof(__half);   // 100KB
    cudaFuncSetAttribute(gemm_kernel,
                         cudaFuncAttributeMaxDynamicSharedMemorySize, (int)smem);
    dim3 grid(ND / BN, MD / BM);   // (32, 64)
    gemm_kernel<<<grid, 128, smem>>>(bias, (float*)d_out);
}

// round 15
// speedup vs baseline: 1.1465x; 1.1465x over previous
#include <cuda_runtime.h>
#include <cuda_fp16.h>
#include <cstdint>

#define KD 4096   // input features
#define ND 4096   // output features
#define MD 8192   // rows of x

// Static device scratch.
static __device__ __half g_W[(size_t)ND * KD];  // dequantized Wt[n][k], 32MB
static __device__ __half g_X[(size_t)MD * KD];  // x fp16, 64MB

// ---------------------------------------------------------------------------
// Merged prologue: blocks [0, 16384) convert x fp32->fp16 (8 elems/thread),
// blocks [16384, 17408) dequant int4 -> fp16 Wt via smem transpose.
// ---------------------------------------------------------------------------
constexpr int CONV_BLOCKS = (int)((size_t)MD * KD / (8 * 256));   // 16384
constexpr int DQ_PADK = 136;   // 128 k halfs + 8 pad -> 272B rows

__global__ void __launch_bounds__(256)
prologue_kernel(const float* __restrict__ x,
                const int* __restrict__ qw,
                const float* __restrict__ scales,
                const float* __restrict__ qzeros) {
    __shared__ __half tile[128 * DQ_PADK];   // 34KB (unused by convert blocks)

    if (blockIdx.x < CONV_BLOCKS) {
        size_t i = ((size_t)blockIdx.x * blockDim.x + threadIdx.x) * 8;
        float4 a = *reinterpret_cast<const float4*>(x + i);
        float4 b = *reinterpret_cast<const float4*>(x + i + 4);
        __half h[8];
        h[0] = __float2half_rn(a.x); h[1] = __float2half_rn(a.y);
        h[2] = __float2half_rn(a.z); h[3] = __float2half_rn(a.w);
        h[4] = __float2half_rn(b.x); h[5] = __float2half_rn(b.y);
        h[6] = __float2half_rn(b.z); h[7] = __float2half_rn(b.w);
        *reinterpret_cast<uint4*>(&g_X[i]) = *reinterpret_cast<const uint4*>(h);
        return;
    }

    const int blk = blockIdx.x - CONV_BLOCKS;     // 0..1023
    const int tid = threadIdx.x;
    const int n0 = (blk & 31) * 128;
    const int r0 = (blk >> 5) * 16;

    const int n_loc = tid & 127;
    const int r_hi  = tid >> 7;
    const int n = n0 + n_loc;

#pragma unroll
    for (int p = 0; p < 8; p++) {
        int r = r0 + r_hi * 8 + p;
        int g = r >> 3;
        uint32_t q = (uint32_t)qw[r * ND + n];
        __half hs = __float2half_rn(scales[g * ND + n]);
        __half hz = __float2half_rn(qzeros[g * ND + n]);
        __half hzs = __hmul(hz, hs);
        __half h[8];
#pragma unroll
        for (int i = 0; i < 8; i++) {
            __half hw = __float2half_rn((float)((q >> (4 * i)) & 15u));
            h[i] = __hsub(__hmul(hs, hw), hzs);
        }
        *reinterpret_cast<uint4*>(&tile[n_loc * DQ_PADK + (r_hi * 8 + p) * 8]) =
            *reinterpret_cast<const uint4*>(h);
    }
    __syncthreads();

    const int wn = tid >> 1;
    const int k0 = r0 * 8;
#pragma unroll
    for (int pass = 0; pass < 8; pass++) {
        int c = (tid & 1) + pass * 2;
        uint4 v = *reinterpret_cast<const uint4*>(&tile[wn * DQ_PADK + c * 8]);
        *reinterpret_cast<uint4*>(&g_W[(size_t)(n0 + wn) * KD + k0 + c * 8]) = v;
    }
}

// ---------------------------------------------------------------------------
// Barrier-free GEMM: C = X * Wt^T + bias. BM=BN=128, BK=32, 4 warps (2x2),
// warp tile 64x64. Each warp stages ITS OWN A-half and B-half into a private
// smem region (XOR-swizzled 64B rows) -> no __syncthreads in the mainloop;
// per-warp cp.async groups + __syncwarp only. 3 stages, 96KB, 2 CTAs/SM.
// ---------------------------------------------------------------------------
constexpr int STAGES = 3;
constexpr int STAGE_STRIDE = 4 * 8192;                // 4 warps x (A 4KB + B 4KB)
constexpr int SMEM_BYTES = STAGES * STAGE_STRIDE;     // 98304 = 96KB

__device__ __forceinline__ void cp16(uint32_t sdst, const void* g) {
    asm volatile("cp.async.cg.shared.global [%0], [%1], 16;\n" :: "r"(sdst), "l"(g));
}

__global__ void __launch_bounds__(128, 2)
gemm_kernel(const float* __restrict__ bias,
            float* __restrict__ C) {
    extern __shared__ __half sm[];
    const uint32_t sb = (uint32_t)__cvta_generic_to_shared(sm);

    const int tid  = threadIdx.x;
    const int lane = tid & 31;
    const int warp = tid >> 5;
    const int wm = warp & 1;
    const int wn = warp >> 1;
    const int bm = blockIdx.y * 128;
    const int bn = blockIdx.x * 128;

    // This warp's global operand rows.
    const __half* gA = g_X + (size_t)(bm + wm * 64) * KD;
    const __half* gB = g_W + (size_t)(bn + wn * 64) * KD;
    const uint32_t wbase = sb + warp * 8192;          // A at +0, B at +4096

    float acc[4][8][4];
#pragma unroll
    for (int i = 0; i < 4; i++)
#pragma unroll
        for (int j = 0; j < 8; j++)
#pragma unroll
            for (int t = 0; t < 4; t++) acc[i][j][t] = 0.f;

    // Per-warp chunk load: 64 rows x 32 halfs for A and B; 16 cp.async/lane.
    // smem addr: r*64 + (c ^ ((r>>1)&3))*16  (conflict-free ldmatrix phases).
    auto load_chunk = [&](int kt, int s) {
        int k0 = kt * 32;
        uint32_t base = wbase + (uint32_t)s * STAGE_STRIDE;
#pragma unroll
        for (int i = 0; i < 8; i++) {
            int idx = i * 32 + lane;      // 0..255
            int r = idx >> 2;             // 0..63
            int c = idx & 3;              // 16B granule
            uint32_t d = (uint32_t)(r * 64 + ((c ^ ((r >> 1) & 3)) * 16));
            cp16(base + d,        gA + (size_t)r * KD + k0 + c * 8);
            cp16(base + 4096 + d, gB + (size_t)r * KD + k0 + c * 8);
        }
        asm volatile("cp.async.commit_group;\n");
    };

    auto compute_stage = [&](int s) {
        uint32_t baseA = wbase + (uint32_t)s * STAGE_STRIDE;
        uint32_t baseB = baseA + 4096;
#pragma unroll
        for (int ks = 0; ks < 2; ks++) {
            uint32_t a[4][4];
            uint32_t b[8][2];
            int arl = lane & 15;
            int cA = 2 * ks + (lane >> 4);
#pragma unroll
            for (int mi = 0; mi < 4; mi++) {
                int r = mi * 16 + arl;
                int g = cA ^ ((r >> 1) & 3);
                uint32_t addr = baseA + (uint32_t)(r * 64 + g * 16);
                asm volatile(
                    "ldmatrix.sync.aligned.m8n8.x4.shared.b16 {%0,%1,%2,%3}, [%4];\n"
                    : "=r"(a[mi][0]), "=r"(a[mi][1]), "=r"(a[mi][2]), "=r"(a[mi][3])
                    : "r"(addr));
            }
            int brl = ((lane >> 4) << 3) + (lane & 7);
            int cB = 2 * ks + ((lane >> 3) & 1);
#pragma unroll
            for (int nh = 0; nh < 4; nh++) {
                int r = nh * 16 + brl;
                int g = cB ^ ((r >> 1) & 3);
                uint32_t addr = baseB + (uint32_t)(r * 64 + g * 16);
                asm volatile(
                    "ldmatrix.sync.aligned.m8n8.x4.shared.b16 {%0,%1,%2,%3}, [%4];\n"
                    : "=r"(b[nh * 2][0]), "=r"(b[nh * 2][1]),
                      "=r"(b[nh * 2 + 1][0]), "=r"(b[nh * 2 + 1][1])
                    : "r"(addr));
            }
#pragma unroll
            for (int mi = 0; mi < 4; mi++)
#pragma unroll
                for (int ni = 0; ni < 8; ni++) {
                    asm volatile(
                        "mma.sync.aligned.m16n8k16.row.col.f32.f16.f16.f32 "
                        "{%0,%1,%2,%3}, {%4,%5,%6,%7}, {%8,%9}, {%0,%1,%2,%3};\n"
                        : "+f"(acc[mi][ni][0]), "+f"(acc[mi][ni][1]),
                          "+f"(acc[mi][ni][2]), "+f"(acc[mi][ni][3])
                        : "r"(a[mi][0]), "r"(a[mi][1]), "r"(a[mi][2]), "r"(a[mi][3]),
                          "r"(b[ni][0]), "r"(b[ni][1]));
                }
        }
    };

    const int KT = KD / 32;   // 128

    load_chunk(0, 0);
    load_chunk(1, 1);

    int cs = 0;               // stage of chunk kt
    int ls = 2;               // stage of chunk kt+2
    for (int kt = 0; kt < KT; kt++) {
        asm volatile("cp.async.wait_group 1;\n");
        __syncwarp();                                  // cross-lane visibility
        if (kt + 2 < KT) load_chunk(kt + 2, ls);
        else             asm volatile("cp.async.commit_group;\n");
        compute_stage(cs);
        if (++cs == STAGES) cs = 0;
        if (++ls == STAGES) ls = 0;
    }

    // Epilogue: fp16(acc) + fp16(bias), store fp32 (mirrors reference rounding).
    const int group = lane >> 2, tig = lane & 3;
#pragma unroll
    for (int mi = 0; mi < 4; mi++) {
        int row = bm + wm * 64 + mi * 16 + group;
#pragma unroll
        for (int ni = 0; ni < 8; ni++) {
            int col = bn + wn * 64 + ni * 8 + tig * 2;
            float2 bb = *reinterpret_cast<const float2*>(&bias[col]);
            __half hb0 = __float2half_rn(bb.x);
            __half hb1 = __float2half_rn(bb.y);
            float2 r0, r1;
            r0.x = __half2float(__hadd(__float2half_rn(acc[mi][ni][0]), hb0));
            r0.y = __half2float(__hadd(__float2half_rn(acc[mi][ni][1]), hb1));
            r1.x = __half2float(__hadd(__float2half_rn(acc[mi][ni][2]), hb0));
            r1.y = __half2float(__hadd(__float2half_rn(acc[mi][ni][3]), hb1));
            *reinterpret_cast<float2*>(&C[(size_t)row * ND + col]) = r0;
            *reinterpret_cast<float2*>(&C[(size_t)(row + 8) * ND + col]) = r1;
        }
    }
}

// ---------------------------------------------------------------------------
extern "C" void kernel_launch(void* const* d_in, const int* in_sizes, int n_in,
                              void* d_out, int out_size) {
    const float* x      = (const float*)d_in[0];
    const int*   qw     = (const int*)d_in[1];
    const float* scales = (const float*)d_in[2];
    const float* qzeros = (const float*)d_in[3];
    const float* bias   = (const float*)d_in[4];

    prologue_kernel<<<CONV_BLOCKS + 1024, 256>>>(x, qw, scales, qzeros);

    cudaFuncSetAttribute(gemm_kernel,
                         cudaFuncAttributeMaxDynamicSharedMemorySize, SMEM_BYTES);
    dim3 grid(ND / 128, MD / 128);   // (32, 64)
    gemm_kernel<<<grid, 128, SMEM_BYTES>>>(bias, (float*)d_out);
}